// round 9
// baseline (speedup 1.0000x reference)
#include <cuda_runtime.h>

#define NB 4
#define NT 4096
#define DE 1024
#define DH 64
#define BT (NB*NT)   // 16384 rows
#define NSL 4        // KV slices per q-tile

typedef unsigned long long ull;

// Scratch: projected Q,K,V (4MB each) + split-KV partials (16MB + 512KB)
__device__ float g_Q[(size_t)BT * DH];
__device__ float g_K[(size_t)BT * DH];
__device__ float g_V[(size_t)BT * DH];
__device__ float g_Op[(size_t)NSL * BT * DH];  // unnormalized partial O
__device__ float g_m[(size_t)NSL * BT];        // running max (log2 domain)
__device__ float g_l[(size_t)NSL * BT];        // running denom

__device__ __forceinline__ float ex2(float x) {
    float y;
    asm("ex2.approx.ftz.f32 %0, %1;" : "=f"(y) : "f"(x));
    return y;
}
__device__ __forceinline__ ull fma2(ull a, ull b, ull c) {
    ull d;
    asm("fma.rn.f32x2 %0, %1, %2, %3;" : "=l"(d) : "l"(a), "l"(b), "l"(c));
    return d;
}
__device__ __forceinline__ ull mul2(ull a, ull b) {
    ull d;
    asm("mul.rn.f32x2 %0, %1, %2;" : "=l"(d) : "l"(a), "l"(b));
    return d;
}
__device__ __forceinline__ ull pack2(float lo, float hi) {
    ull d;
    asm("mov.b64 %0, {%1, %2};" : "=l"(d) : "f"(lo), "f"(hi));
    return d;
}
__device__ __forceinline__ void unpack2(ull v, float& lo, float& hi) {
    asm("mov.b64 {%0, %1}, %2;" : "=f"(lo), "=f"(hi) : "l"(v));
}

// ===================== Kernel 1: FUSED QKV projection =====================
// One pass over X computes Q, K and V: BM=64 rows x BN=192 cols (64 each),
// BK=32, 256 threads. Per-thread: 4 rows x 12 cols = 4x6 f32x2 (col pairs
// in lanes; b-side loads naturally paired, a-side scalars duplicated).
// X gmem traffic: read ONCE (64MB) instead of 3x.
__global__ __launch_bounds__(256) void qkv_fused_kernel(
    const float* __restrict__ x,
    const float* __restrict__ Wk,
    const float* __restrict__ Wq,
    const float* __restrict__ Wv)
{
    __shared__ float Xs[32][68];    // [k][row 0..63], pad 272B=17*16
    __shared__ float Ws[32][200];   // [k][col 0..191], pad 800B=50*16

    const int tid = threadIdx.x;
    const int tx = tid & 15;        // 0..15 -> 12 cols each
    const int ty = tid >> 4;        // 0..15 -> 4 rows each
    const int rowBase = blockIdx.x * 64;

    ull c2[4][6];   // [row][colpair], lanes = (col 2p, col 2p+1)
#pragma unroll
    for (int i = 0; i < 4; i++)
#pragma unroll
        for (int p = 0; p < 6; p++) c2[i][p] = 0ull;

    for (int kc = 0; kc < DE; kc += 32) {
        // X tile (64x32) transposed into Xs[k][row]: 512 float4s
#pragma unroll
        for (int i = 0; i < 2; i++) {
            int idx4 = tid + i * 256;          // 0..511
            int row = idx4 >> 3;               // 0..63
            int kq  = idx4 & 7;                // 0..7
            float4 v = *(const float4*)(x + (size_t)(rowBase + row) * DE + kc + kq * 4);
            Xs[kq*4+0][row] = v.x;
            Xs[kq*4+1][row] = v.y;
            Xs[kq*4+2][row] = v.z;
            Xs[kq*4+3][row] = v.w;
        }
        // W tile (192x32) transposed into Ws[k][col]: cols 0-63=Q, 64-127=K, 128-191=V
#pragma unroll
        for (int i = 0; i < 6; i++) {
            int idx4 = tid + i * 256;          // 0..1535
            int wrow = idx4 >> 3;              // 0..191
            int kq   = idx4 & 7;
            const float* src = (wrow < 64) ? (Wq + (size_t)wrow * DE)
                             : (wrow < 128) ? (Wk + (size_t)(wrow - 64) * DE)
                                            : (Wv + (size_t)(wrow - 128) * DE);
            float4 v = *(const float4*)(src + kc + kq * 4);
            Ws[kq*4+0][wrow] = v.x;
            Ws[kq*4+1][wrow] = v.y;
            Ws[kq*4+2][wrow] = v.z;
            Ws[kq*4+3][wrow] = v.w;
        }
        __syncthreads();
#pragma unroll 8
        for (int k = 0; k < 32; k++) {
            float4 av = *(const float4*)&Xs[k][ty*4];
            ull a2[4] = {pack2(av.x, av.x), pack2(av.y, av.y),
                         pack2(av.z, av.z), pack2(av.w, av.w)};
            ulonglong2 b01 = *(const ulonglong2*)&Ws[k][tx*12];
            ulonglong2 b23 = *(const ulonglong2*)&Ws[k][tx*12 + 4];
            ulonglong2 b45 = *(const ulonglong2*)&Ws[k][tx*12 + 8];
            ull b2[6] = {b01.x, b01.y, b23.x, b23.y, b45.x, b45.y};
#pragma unroll
            for (int i = 0; i < 4; i++) {
#pragma unroll
                for (int p = 0; p < 6; p++)
                    c2[i][p] = fma2(a2[i], b2[p], c2[i][p]);
            }
        }
        __syncthreads();
    }
    // Store: each float4 chunk lies entirely inside one 64-col block (4 | boundaries)
#pragma unroll
    for (int i = 0; i < 4; i++) {
        const size_t row = (size_t)(rowBase + ty*4 + i);
#pragma unroll
        for (int j = 0; j < 3; j++) {
            int c = tx*12 + j*4;
            int sel = c >> 6;
            int local = c & 63;
            float* out = (sel == 0) ? g_Q : (sel == 1) ? g_K : g_V;
            float f0, f1, f2, f3;
            unpack2(c2[i][j*2],   f0, f1);
            unpack2(c2[i][j*2+1], f2, f3);
            *(float4*)(out + row * DH + local) = make_float4(f0, f1, f2, f3);
        }
    }
}

// ===================== Kernel 2: split-KV causal flash attention =====================
// R2-verified structure (BQ=BKV=64, 256 threads, 4x4 tiles, 48KB smem) with
// jj-pairs packed in f32x2: accumulators s2[4][2] / o2[4][2]; K/V pairs load
// naturally as ulonglong2, only broadcast scalars get packed.
// Grid = (64 q-tiles, 4 batches, 4 KV-slices); partials merged by combine_kernel.
#define SCL (0.125f * 1.4426950408889634f)   // 1/sqrt(64) * log2(e)

__global__ __launch_bounds__(256) void attn_partial()
{
    __shared__ float Qs[64*64];  // [h][i] transposed
    __shared__ float Xb[64*64];  // K as [h][j], then P as [i][j]
    __shared__ float Vs[64*64];  // [t][h] natural

    const int tid = threadIdx.x;
    const int tx = tid & 15;   // j / d groups of 4
    const int ty = tid >> 4;   // i groups of 4
    const int qt = blockIdx.x;            // 0..63
    const size_t bb = (size_t)blockIdx.y * NT;
    const int sl = blockIdx.z;            // 0..3
    const int qbase = qt * 64;

    const int nkv = qt + 1;
    const int len = (nkv + NSL - 1) / NSL;
    const int kv0 = sl * len;
    const int kv1 = (kv0 + len < nkv) ? (kv0 + len) : nkv;

    float m[4], l[4];
    ull o2[4][2];
#pragma unroll
    for (int i = 0; i < 4; i++) {
        m[i] = -1e30f; l[i] = 0.f;
        o2[i][0] = 0ull; o2[i][1] = 0ull;
    }

    const size_t pbase = (size_t)sl * BT + bb + qbase;

    if (kv0 < kv1) {
        // Load Q tile transposed, pre-scaled by 1/sqrt(d)*log2e
#pragma unroll
        for (int i = 0; i < 4; i++) {
            int idx4 = tid + i * 256;
            int r  = idx4 >> 4;     // 0..63 token
            int hq = idx4 & 15;     // float4 within head dim
            float4 v = *(const float4*)(g_Q + (bb + qbase + r) * DH + hq * 4);
            Qs[(hq*4+0)*64 + r] = v.x * SCL;
            Qs[(hq*4+1)*64 + r] = v.y * SCL;
            Qs[(hq*4+2)*64 + r] = v.z * SCL;
            Qs[(hq*4+3)*64 + r] = v.w * SCL;
        }

        for (int kt = kv0; kt < kv1; kt++) {
            const int kbase = kt * 64;
            // Load K (transposed into Xb) and V (natural into Vs)
#pragma unroll
            for (int i = 0; i < 4; i++) {
                int idx4 = tid + i * 256;
                int r  = idx4 >> 4;
                int hq = idx4 & 15;
                float4 v = *(const float4*)(g_K + (bb + kbase + r) * DH + hq * 4);
                Xb[(hq*4+0)*64 + r] = v.x;
                Xb[(hq*4+1)*64 + r] = v.y;
                Xb[(hq*4+2)*64 + r] = v.z;
                Xb[(hq*4+3)*64 + r] = v.w;
                float4 w = *(const float4*)(g_V + (bb + kbase + r) * DH + hq * 4);
                *(float4*)&Vs[r*64 + hq*4] = w;
            }
            __syncthreads();   // tiles (and Qs on first iter) visible

            // S tile (f32x2, jj-pairs): s2[ii][p] lanes = cols (4tx+2p, 4tx+2p+1)
            ull s2[4][2];
#pragma unroll
            for (int ii = 0; ii < 4; ii++) { s2[ii][0] = 0ull; s2[ii][1] = 0ull; }
#pragma unroll 8
            for (int h = 0; h < 64; h++) {
                float4 qa = *(const float4*)&Qs[h*64 + ty*4];
                ulonglong2 kb = *(const ulonglong2*)&Xb[h*64 + tx*4];
                ull a2[4] = {pack2(qa.x, qa.x), pack2(qa.y, qa.y),
                             pack2(qa.z, qa.z), pack2(qa.w, qa.w)};
#pragma unroll
                for (int ii = 0; ii < 4; ii++) {
                    s2[ii][0] = fma2(a2[ii], kb.x, s2[ii][0]);
                    s2[ii][1] = fma2(a2[ii], kb.y, s2[ii][1]);
                }
            }

            float s[4][4];
#pragma unroll
            for (int ii = 0; ii < 4; ii++) {
                unpack2(s2[ii][0], s[ii][0], s[ii][1]);
                unpack2(s2[ii][1], s[ii][2], s[ii][3]);
            }

            // Causal mask (only on the diagonal tile)
            if (kt == qt) {
#pragma unroll
                for (int ii = 0; ii < 4; ii++)
#pragma unroll
                    for (int jj = 0; jj < 4; jj++)
                        if (tx*4 + jj > ty*4 + ii) s[ii][jj] = -1e30f;
            }

            __syncthreads();  // all threads done reading Xb as K

            // Online softmax; write P into Xb[i][j]
#pragma unroll
            for (int ii = 0; ii < 4; ii++) {
                float tmax = fmaxf(fmaxf(s[ii][0], s[ii][1]), fmaxf(s[ii][2], s[ii][3]));
#pragma unroll
                for (int w = 1; w < 16; w <<= 1)
                    tmax = fmaxf(tmax, __shfl_xor_sync(0xffffffffu, tmax, w));
                float mn = fmaxf(m[ii], tmax);
                float corr = ex2(m[ii] - mn);
                m[ii] = mn;
                float rs = 0.f;
#pragma unroll
                for (int jj = 0; jj < 4; jj++) {
                    float p = ex2(s[ii][jj] - mn);
                    s[ii][jj] = p;
                    rs += p;
                }
#pragma unroll
                for (int w = 1; w < 16; w <<= 1)
                    rs += __shfl_xor_sync(0xffffffffu, rs, w);
                l[ii] = l[ii] * corr + rs;
                ull corr2 = pack2(corr, corr);
                o2[ii][0] = mul2(o2[ii][0], corr2);
                o2[ii][1] = mul2(o2[ii][1], corr2);
                *(float4*)&Xb[(ty*4+ii)*64 + tx*4] =
                    make_float4(s[ii][0], s[ii][1], s[ii][2], s[ii][3]);
            }
            __syncthreads();  // P visible

            // O += P @ V   (o2[ii][p] lanes = head dims (4tx+2p, 4tx+2p+1))
#pragma unroll 8
            for (int kv = 0; kv < 64; kv++) {
                ulonglong2 vv = *(const ulonglong2*)&Vs[kv*64 + tx*4];
                float pa[4];
#pragma unroll
                for (int ii = 0; ii < 4; ii++) pa[ii] = Xb[(ty*4+ii)*64 + kv];
#pragma unroll
                for (int ii = 0; ii < 4; ii++) {
                    ull p2 = pack2(pa[ii], pa[ii]);
                    o2[ii][0] = fma2(p2, vv.x, o2[ii][0]);
                    o2[ii][1] = fma2(p2, vv.y, o2[ii][1]);
                }
            }
            __syncthreads();  // done with Xb/Vs before next tile load
        }
    }

    // Epilogue: write UNNORMALIZED partials + (m, l) per row
#pragma unroll
    for (int ii = 0; ii < 4; ii++) {
        int r = ty*4 + ii;
        float f0, f1, f2, f3;
        unpack2(o2[ii][0], f0, f1);
        unpack2(o2[ii][1], f2, f3);
        *(float4*)(g_Op + (pbase + r) * DH + tx*4) = make_float4(f0, f1, f2, f3);
        if (tx == 0) {
            g_m[pbase + r] = m[ii];
            g_l[pbase + r] = l[ii];
        }
    }
}

// ===================== Kernel 3: split-softmax combine =====================
// One thread per (row, float4-chunk): 16384 * 16 threads.
__global__ __launch_bounds__(256) void combine_kernel(float* __restrict__ out)
{
    int idx = blockIdx.x * 256 + threadIdx.x;   // 0 .. BT*16-1
    int r  = idx >> 4;
    int c4 = idx & 15;

    float m0 = g_m[r], m1 = g_m[BT + r], m2 = g_m[2*BT + r], m3 = g_m[3*BT + r];
    float M = fmaxf(fmaxf(m0, m1), fmaxf(m2, m3));
    float w0 = ex2(m0 - M), w1 = ex2(m1 - M), w2 = ex2(m2 - M), w3 = ex2(m3 - M);
    float L = g_l[r]*w0 + g_l[BT + r]*w1 + g_l[2*BT + r]*w2 + g_l[3*BT + r]*w3;
    float inv = 1.f / L;

    size_t off = (size_t)r * DH + c4 * 4;
    float4 a0 = *(const float4*)(g_Op + off);
    float4 a1 = *(const float4*)(g_Op + (size_t)BT*DH   + off);
    float4 a2 = *(const float4*)(g_Op + (size_t)2*BT*DH + off);
    float4 a3 = *(const float4*)(g_Op + (size_t)3*BT*DH + off);

    float4 res;
    res.x = (a0.x*w0 + a1.x*w1 + a2.x*w2 + a3.x*w3) * inv;
    res.y = (a0.y*w0 + a1.y*w1 + a2.y*w2 + a3.y*w3) * inv;
    res.z = (a0.z*w0 + a1.z*w1 + a2.z*w2 + a3.z*w3) * inv;
    res.w = (a0.w*w0 + a1.w*w1 + a2.w*w2 + a3.w*w3) * inv;
    *(float4*)(out + off) = res;
}

extern "C" void kernel_launch(void* const* d_in, const int* in_sizes, int n_in,
                              void* d_out, int out_size) {
    const float* x  = (const float*)d_in[0];
    const float* Wk = (const float*)d_in[1];
    const float* Wq = (const float*)d_in[2];
    const float* Wv = (const float*)d_in[3];
    float* out = (float*)d_out;

    qkv_fused_kernel<<<BT/64, 256>>>(x, Wk, Wq, Wv);
    attn_partial<<<dim3(64, NB, NSL), 256>>>();
    combine_kernel<<<(BT*16)/256, 256>>>(out);

    (void)in_sizes; (void)n_in; (void)out_size;
}

// round 16
// speedup vs baseline: 1.0578x; 1.0578x over previous
#include <cuda_runtime.h>

#define NB 4
#define NT 4096
#define DE 1024
#define DH 64
#define BT (NB*NT)   // 16384 rows
#define NSL 4        // KV slices per q-tile

typedef unsigned long long ull;

// Scratch: projected Q,K,V (4MB each) + split-KV partials (16MB + 512KB)
__device__ float g_Q[(size_t)BT * DH];
__device__ float g_K[(size_t)BT * DH];
__device__ float g_V[(size_t)BT * DH];
__device__ float g_Op[(size_t)NSL * BT * DH];  // unnormalized partial O
__device__ float g_m[(size_t)NSL * BT];        // running max (log2 domain)
__device__ float g_l[(size_t)NSL * BT];        // running denom

__device__ __forceinline__ float ex2(float x) {
    float y;
    asm("ex2.approx.ftz.f32 %0, %1;" : "=f"(y) : "f"(x));
    return y;
}
__device__ __forceinline__ ull fma2(ull a, ull b, ull c) {
    ull d;
    asm("fma.rn.f32x2 %0, %1, %2, %3;" : "=l"(d) : "l"(a), "l"(b), "l"(c));
    return d;
}
__device__ __forceinline__ ull mul2(ull a, ull b) {
    ull d;
    asm("mul.rn.f32x2 %0, %1, %2;" : "=l"(d) : "l"(a), "l"(b));
    return d;
}
__device__ __forceinline__ ull pack2(float lo, float hi) {
    ull d;
    asm("mov.b64 %0, {%1, %2};" : "=l"(d) : "f"(lo), "f"(hi));
    return d;
}
__device__ __forceinline__ void unpack2(ull v, float& lo, float& hi) {
    asm("mov.b64 {%0, %1}, %2;" : "=f"(lo), "=f"(hi) : "l"(v));
}

// ===================== Kernel 1: QKV projection (R8-verified, 171.9us) =====================
__global__ __launch_bounds__(256) void qkv_kernel(
    const float* __restrict__ x,
    const float* __restrict__ Wk,
    const float* __restrict__ Wq,
    const float* __restrict__ Wv)
{
    __shared__ float Xs[32][132];  // [k][row], padded
    __shared__ float Ws[32][68];   // [k][col], padded

    const float* __restrict__ W;
    float* out;
    const int sel = blockIdx.y;
    if (sel == 0)      { W = Wq; out = g_Q; }
    else if (sel == 1) { W = Wk; out = g_K; }
    else               { W = Wv; out = g_V; }

    const int tid = threadIdx.x;
    const int tx = tid & 15;
    const int ty = tid >> 4;
    const int rowBase = blockIdx.x * 128;

    ull acc2[4][4];
#pragma unroll
    for (int p = 0; p < 4; p++)
#pragma unroll
        for (int j = 0; j < 4; j++) acc2[p][j] = 0ull;

    for (int kc = 0; kc < DE; kc += 32) {
#pragma unroll
        for (int i = 0; i < 4; i++) {
            int idx4 = tid + i * 256;
            int row = idx4 >> 3;
            int kq  = idx4 & 7;
            float4 v = *(const float4*)(x + (size_t)(rowBase + row) * DE + kc + kq * 4);
            Xs[kq*4+0][row] = v.x;
            Xs[kq*4+1][row] = v.y;
            Xs[kq*4+2][row] = v.z;
            Xs[kq*4+3][row] = v.w;
        }
#pragma unroll
        for (int i = 0; i < 2; i++) {
            int idx4 = tid + i * 256;
            int wrow = idx4 >> 3;
            int kq   = idx4 & 7;
            float4 v = *(const float4*)(W + (size_t)wrow * DE + kc + kq * 4);
            Ws[kq*4+0][wrow] = v.x;
            Ws[kq*4+1][wrow] = v.y;
            Ws[kq*4+2][wrow] = v.z;
            Ws[kq*4+3][wrow] = v.w;
        }
        __syncthreads();
#pragma unroll 8
        for (int k = 0; k < 32; k++) {
            ulonglong2 a01 = *(const ulonglong2*)&Xs[k][ty*8];
            ulonglong2 a23 = *(const ulonglong2*)&Xs[k][ty*8+4];
            ull a2[4] = {a01.x, a01.y, a23.x, a23.y};
            float4 bv = *(const float4*)&Ws[k][tx*4];
            ull b2[4] = {pack2(bv.x, bv.x), pack2(bv.y, bv.y),
                         pack2(bv.z, bv.z), pack2(bv.w, bv.w)};
#pragma unroll
            for (int p = 0; p < 4; p++) {
                acc2[p][0] = fma2(a2[p], b2[0], acc2[p][0]);
                acc2[p][1] = fma2(a2[p], b2[1], acc2[p][1]);
                acc2[p][2] = fma2(a2[p], b2[2], acc2[p][2]);
                acc2[p][3] = fma2(a2[p], b2[3], acc2[p][3]);
            }
        }
        __syncthreads();
    }
#pragma unroll
    for (int p = 0; p < 4; p++) {
        float e[4], o[4];
#pragma unroll
        for (int j = 0; j < 4; j++) unpack2(acc2[p][j], e[j], o[j]);
        *(float4*)(out + (size_t)(rowBase + ty*8 + 2*p)     * DH + tx*4) =
            make_float4(e[0], e[1], e[2], e[3]);
        *(float4*)(out + (size_t)(rowBase + ty*8 + 2*p + 1) * DH + tx*4) =
            make_float4(o[0], o[1], o[2], o[3]);
    }
}

// ===================== Kernel 2: split-KV flash attention, 8x8 tiles =====================
// BQ=64, BKV=128 per chunk. 128 threads: tx=tid&15 (8 cols each), ty=tid>>4
// (8 rows each). 1 B/MAC smem intensity. PV: tx<8 handles kv[0,64), tx>=8
// kv[64,128); halves merged at epilogue (m/l are row-global, so consistent).
// Dynamic smem 80KB: Qs[h][i] 16K | Kb[h][j] 32K (aliased by P[i][j]) | Vs 32K.
#define SCL (0.125f * 1.4426950408889634f)   // 1/sqrt(64) * log2(e)

__global__ __launch_bounds__(128) void attn_partial()
{
    extern __shared__ float sm[];
    float* Qs = sm;            // 64*64
    float* Kb = sm + 4096;     // 64*128  (K as [h][j]; later P as [i][j])
    float* Vs = sm + 12288;    // 128*64  ([t][d])

    const int tid = threadIdx.x;
    const int tx = tid & 15;   // col groups of 8 (S); (half, d-group) for PV
    const int ty = tid >> 4;   // row groups of 8
    const int qt = blockIdx.x;            // 0..63
    const size_t bb = (size_t)blockIdx.y * NT;
    const int sl = blockIdx.z;            // 0..3
    const int qbase = qt * 64;

    const int nc  = (qt + 2) >> 1;                 // 128-token chunks (1..32)
    const int len = (nc + NSL - 1) / NSL;
    const int c0  = sl * len;
    const int c1  = (c0 + len < nc) ? (c0 + len) : nc;

    float m[8], l[8];
    ull o2[8][4];
#pragma unroll
    for (int i = 0; i < 8; i++) {
        m[i] = -1e30f; l[i] = 0.f;
#pragma unroll
        for (int p = 0; p < 4; p++) o2[i][p] = 0ull;
    }

    const size_t pbase = (size_t)sl * BT + bb + qbase;
    const int half = tx >> 3, txd = tx & 7;

    if (c0 < c1) {
        // Q tile transposed [h][i], pre-scaled
#pragma unroll
        for (int i = 0; i < 8; i++) {
            int idx4 = tid + i * 128;   // 0..1023
            int r  = idx4 >> 4;
            int hq = idx4 & 15;
            float4 v = *(const float4*)(g_Q + (bb + qbase + r) * DH + hq * 4);
            Qs[(hq*4+0)*64 + r] = v.x * SCL;
            Qs[(hq*4+1)*64 + r] = v.y * SCL;
            Qs[(hq*4+2)*64 + r] = v.z * SCL;
            Qs[(hq*4+3)*64 + r] = v.w * SCL;
        }

        for (int c = c0; c < c1; c++) {
            const int kb = c * 128;
            // K transposed [h][j 0..127]; V natural [t][d]
#pragma unroll
            for (int i = 0; i < 16; i++) {
                int idx4 = tid + i * 128;   // 0..2047
                int t  = idx4 >> 4;         // 0..127
                int hq = idx4 & 15;
                float4 v = *(const float4*)(g_K + (bb + kb + t) * DH + hq * 4);
                Kb[(hq*4+0)*128 + t] = v.x;
                Kb[(hq*4+1)*128 + t] = v.y;
                Kb[(hq*4+2)*128 + t] = v.z;
                Kb[(hq*4+3)*128 + t] = v.w;
                float4 w = *(const float4*)(g_V + (bb + kb + t) * DH + hq * 4);
                *(float4*)&Vs[t*64 + hq*4] = w;
            }
            __syncthreads();   // tiles (and Qs on first iter) visible

            // S: s2[ii][p] lanes = cols (tx*8+2p, tx*8+2p+1)
            ull s2[8][4];
#pragma unroll
            for (int ii = 0; ii < 8; ii++)
#pragma unroll
                for (int p = 0; p < 4; p++) s2[ii][p] = 0ull;
#pragma unroll 4
            for (int h = 0; h < 64; h++) {
                float4 qa = *(const float4*)&Qs[h*64 + ty*8];
                float4 qb = *(const float4*)&Qs[h*64 + ty*8 + 4];
                ull a2[8] = {pack2(qa.x,qa.x), pack2(qa.y,qa.y),
                             pack2(qa.z,qa.z), pack2(qa.w,qa.w),
                             pack2(qb.x,qb.x), pack2(qb.y,qb.y),
                             pack2(qb.z,qb.z), pack2(qb.w,qb.w)};
                ulonglong2 k01 = *(const ulonglong2*)&Kb[h*128 + tx*8];
                ulonglong2 k23 = *(const ulonglong2*)&Kb[h*128 + tx*8 + 4];
                ull b2[4] = {k01.x, k01.y, k23.x, k23.y};
#pragma unroll
                for (int ii = 0; ii < 8; ii++) {
                    s2[ii][0] = fma2(a2[ii], b2[0], s2[ii][0]);
                    s2[ii][1] = fma2(a2[ii], b2[1], s2[ii][1]);
                    s2[ii][2] = fma2(a2[ii], b2[2], s2[ii][2]);
                    s2[ii][3] = fma2(a2[ii], b2[3], s2[ii][3]);
                }
            }
            __syncthreads();  // all threads done reading Kb as K (P overwrites it)

            const bool needMask = (kb + 127 > qbase);
            // Softmax per row; write P into Kb as [i][j]
#pragma unroll
            for (int ii = 0; ii < 8; ii++) {
                float s[8];
                unpack2(s2[ii][0], s[0], s[1]);
                unpack2(s2[ii][1], s[2], s[3]);
                unpack2(s2[ii][2], s[4], s[5]);
                unpack2(s2[ii][3], s[6], s[7]);
                if (needMask) {
                    int rg = qbase + ty*8 + ii;
#pragma unroll
                    for (int jl = 0; jl < 8; jl++)
                        if (kb + tx*8 + jl > rg) s[jl] = -1e30f;
                }
                float tmax = s[0];
#pragma unroll
                for (int jl = 1; jl < 8; jl++) tmax = fmaxf(tmax, s[jl]);
#pragma unroll
                for (int w = 1; w < 16; w <<= 1)
                    tmax = fmaxf(tmax, __shfl_xor_sync(0xffffffffu, tmax, w, 16));
                float mn = fmaxf(m[ii], tmax);
                float corr = ex2(m[ii] - mn);
                m[ii] = mn;
                float rs = 0.f;
#pragma unroll
                for (int jl = 0; jl < 8; jl++) {
                    float p = ex2(s[jl] - mn);
                    s[jl] = p;
                    rs += p;
                }
#pragma unroll
                for (int w = 1; w < 16; w <<= 1)
                    rs += __shfl_xor_sync(0xffffffffu, rs, w, 16);
                l[ii] = l[ii] * corr + rs;
                ull corr2 = pack2(corr, corr);
#pragma unroll
                for (int p = 0; p < 4; p++) o2[ii][p] = mul2(o2[ii][p], corr2);
                *(float4*)&Kb[(ty*8+ii)*128 + tx*8]     = make_float4(s[0], s[1], s[2], s[3]);
                *(float4*)&Kb[(ty*8+ii)*128 + tx*8 + 4] = make_float4(s[4], s[5], s[6], s[7]);
            }
            __syncthreads();  // P visible

            // O += P @ V over this thread's kv-half; d-cols txd*8..+7
#pragma unroll 4
            for (int kvl = 0; kvl < 64; kvl++) {
                int kv = half*64 + kvl;
                ulonglong2 v01 = *(const ulonglong2*)&Vs[kv*64 + txd*8];
                ulonglong2 v23 = *(const ulonglong2*)&Vs[kv*64 + txd*8 + 4];
                ull b2[4] = {v01.x, v01.y, v23.x, v23.y};
#pragma unroll
                for (int ii = 0; ii < 8; ii++) {
                    float p = Kb[(ty*8+ii)*128 + kv];
                    ull p2 = pack2(p, p);
                    o2[ii][0] = fma2(p2, b2[0], o2[ii][0]);
                    o2[ii][1] = fma2(p2, b2[1], o2[ii][1]);
                    o2[ii][2] = fma2(p2, b2[2], o2[ii][2]);
                    o2[ii][3] = fma2(p2, b2[3], o2[ii][3]);
                }
            }
            __syncthreads();  // done with Kb/Vs before next chunk load
        }
    }

    // Epilogue: merge kv-halves (partner lane = tx^8), store partials + (m,l)
#pragma unroll
    for (int ii = 0; ii < 8; ii++) {
        float of[8];
#pragma unroll
        for (int p = 0; p < 4; p++) {
            ull other = __shfl_xor_sync(0xffffffffu, o2[ii][p], 8, 32);
            float a0, a1, b0, b1;
            unpack2(o2[ii][p], a0, a1);
            unpack2(other,     b0, b1);
            of[2*p]   = a0 + b0;
            of[2*p+1] = a1 + b1;
        }
        int r = ty*8 + ii;
        if (half == 0) {
            *(float4*)(g_Op + (pbase + r) * DH + txd*8) =
                make_float4(of[0], of[1], of[2], of[3]);
            *(float4*)(g_Op + (pbase + r) * DH + txd*8 + 4) =
                make_float4(of[4], of[5], of[6], of[7]);
        }
        if (tx == 0) {
            g_m[pbase + r] = m[ii];
            g_l[pbase + r] = l[ii];
        }
    }
}

// ===================== Kernel 3: split-softmax combine =====================
__global__ __launch_bounds__(256) void combine_kernel(float* __restrict__ out)
{
    int idx = blockIdx.x * 256 + threadIdx.x;   // 0 .. BT*16-1
    int r  = idx >> 4;
    int c4 = idx & 15;

    float m0 = g_m[r], m1 = g_m[BT + r], m2 = g_m[2*BT + r], m3 = g_m[3*BT + r];
    float M = fmaxf(fmaxf(m0, m1), fmaxf(m2, m3));
    float w0 = ex2(m0 - M), w1 = ex2(m1 - M), w2 = ex2(m2 - M), w3 = ex2(m3 - M);
    float L = g_l[r]*w0 + g_l[BT + r]*w1 + g_l[2*BT + r]*w2 + g_l[3*BT + r]*w3;
    float inv = 1.f / L;

    size_t off = (size_t)r * DH + c4 * 4;
    float4 a0 = *(const float4*)(g_Op + off);
    float4 a1 = *(const float4*)(g_Op + (size_t)BT*DH   + off);
    float4 a2 = *(const float4*)(g_Op + (size_t)2*BT*DH + off);
    float4 a3 = *(const float4*)(g_Op + (size_t)3*BT*DH + off);

    float4 res;
    res.x = (a0.x*w0 + a1.x*w1 + a2.x*w2 + a3.x*w3) * inv;
    res.y = (a0.y*w0 + a1.y*w1 + a2.y*w2 + a3.y*w3) * inv;
    res.z = (a0.z*w0 + a1.z*w1 + a2.z*w2 + a3.z*w3) * inv;
    res.w = (a0.w*w0 + a1.w*w1 + a2.w*w2 + a3.w*w3) * inv;
    *(float4*)(out + off) = res;
}

extern "C" void kernel_launch(void* const* d_in, const int* in_sizes, int n_in,
                              void* d_out, int out_size) {
    const float* x  = (const float*)d_in[0];
    const float* Wk = (const float*)d_in[1];
    const float* Wq = (const float*)d_in[2];
    const float* Wv = (const float*)d_in[3];
    float* out = (float*)d_out;

    static int attr_set = 0;
    if (!attr_set) {
        cudaFuncSetAttribute(attn_partial,
                             cudaFuncAttributeMaxDynamicSharedMemorySize, 81920);
        attr_set = 1;
    }

    qkv_kernel<<<dim3(BT/128, 3), 256>>>(x, Wk, Wq, Wv);
    attn_partial<<<dim3(64, NB, NSL), 128, 81920>>>();
    combine_kernel<<<(BT*16)/256, 256>>>(out);

    (void)in_sizes; (void)n_in; (void)out_size;
}